// round 1
// baseline (speedup 1.0000x reference)
#include <cuda_runtime.h>

#define BB 4
#define CC 64
#define HH 256
#define WW 256
#define HWSZ 65536
#define NPTS 16384
#define NT 256

// Per-point transposed table: [B*N][68] = feat3d(64) | flow3d(2) | xy(2)
__device__ float g_T[BB * NPTS * 68];

__global__ void prep_kernel(const float* __restrict__ xy,
                            const float* __restrict__ feat3d,
                            const float* __restrict__ flow3d) {
    int gp = blockIdx.x * blockDim.x + threadIdx.x;   // 0 .. B*N-1
    if (gp >= BB * NPTS) return;
    int b = gp >> 14;
    int p = gp & (NPTS - 1);
    float* dst = g_T + (size_t)gp * 68;
    const float* src = feat3d + (size_t)b * CC * NPTS + p;
#pragma unroll
    for (int c = 0; c < 64; c++) dst[c] = src[c * NPTS];
    dst[64] = flow3d[((size_t)b * 2 + 0) * NPTS + p];
    dst[65] = flow3d[((size_t)b * 2 + 1) * NPTS + p];
    dst[66] = xy[((size_t)b * 2 + 0) * NPTS + p];
    dst[67] = xy[((size_t)b * 2 + 1) * NPTS + p];
}

// Dynamic smem layout (floats):
//  sw1 : 64*72   (w1 padded 69->72, zero-filled)
//  sw2 : 64*64
//  sw3 : 64*64
//  swf : 64*128
//  sb  : 256     (b1|b2|b3|bf)
//  act : 64*NT   (per-thread activation bounce buffer)
//  f2b : 64*NT   (per-thread feat_2d cache for layer 4)
#define SMEM_FLOATS (64*72 + 64*64 + 64*64 + 64*128 + 256 + 64*NT + 64*NT)

__global__ __launch_bounds__(NT, 1)
void fused_kernel(const float* __restrict__ feat2d,
                  const float* __restrict__ lf2d,
                  const int*   __restrict__ nnp,
                  const float* __restrict__ w1, const float* __restrict__ b1,
                  const float* __restrict__ w2, const float* __restrict__ b2,
                  const float* __restrict__ w3, const float* __restrict__ b3,
                  const float* __restrict__ wf, const float* __restrict__ bf,
                  float* __restrict__ out) {
    extern __shared__ float sm[];
    float* sw1 = sm;                 // 4608
    float* sw2 = sw1 + 64 * 72;      // 4096
    float* sw3 = sw2 + 4096;         // 4096
    float* swf = sw3 + 4096;         // 8192
    float* sb  = swf + 8192;         // 256
    float* act = sb + 256;           // 64*NT
    float* f2b = act + 64 * NT;      // 64*NT

    const int tid = threadIdx.x;

    // ---- cooperative weight load (broadcast-read later) ----
    for (int i = tid; i < 64 * 72; i += NT) {
        int o = i / 72, k = i - o * 72;
        sw1[i] = (k < 69) ? w1[o * 69 + k] : 0.0f;
    }
    for (int i = tid; i < 4096; i += NT) { sw2[i] = w2[i]; sw3[i] = w3[i]; }
    for (int i = tid; i < 8192; i += NT) { swf[i] = wf[i]; }
    if (tid < 64) {
        sb[tid]       = b1[tid];
        sb[64 + tid]  = b2[tid];
        sb[128 + tid] = b3[tid];
        sb[192 + tid] = bf[tid];
    }
    __syncthreads();

    const int pixel = blockIdx.x * NT + tid;      // 0 .. 262143
    const int b   = pixel >> 16;
    const int pix = pixel & (HWSZ - 1);
    const int wi  = pix & (WW - 1);
    const int hi  = pix >> 8;

    const int idx = nnp[pixel];                    // [B,H,W,1] -> b*HW+pix == pixel
    const float* t = g_T + (size_t)(b * NPTS + idx) * 68;

    // ---- assemble layer-1 input x[0..68] (padded to 72) ----
    float a[72];
#pragma unroll
    for (int k = 0; k < 64; k += 4) {
        float4 v = *(const float4*)(t + k);
        a[3 + k] = v.x; a[4 + k] = v.y; a[5 + k] = v.z; a[6 + k] = v.w;
    }
    {
        float4 tv = *(const float4*)(t + 64);     // fl0, fl1, xyx, xyy
        a[1] = tv.z - (float)wi;                  // offset x (xy_proj - grid_x)
        a[2] = tv.w - (float)hi;                  // offset y
        const float* lf = lf2d + (size_t)b * 2 * HWSZ + pix;
        a[67] = tv.x - lf[0];                     // flow_ch x
        a[68] = tv.y - lf[HWSZ];                  // flow_ch y
    }
    a[69] = 0.0f; a[70] = 0.0f; a[71] = 0.0f;

    // ---- corr = mean_c( gathered_c * feat2d_c ); cache feat2d in smem ----
    {
        const float* f2 = feat2d + (size_t)b * CC * HWSZ + pix;
        float corr = 0.0f;
#pragma unroll
        for (int c = 0; c < 64; c++) {
            float v = __ldg(&f2[c * HWSZ]);
            corr += a[3 + c] * v;
            f2b[c * NT + tid] = v;
        }
        a[0] = corr * (1.0f / 64.0f);
    }

    // ---- layer 1: 69 -> 64 ----
#pragma unroll 1
    for (int oc = 0; oc < 64; oc += 8) {
        float acc[8];
#pragma unroll
        for (int j = 0; j < 8; j++) acc[j] = sb[oc + j];
#pragma unroll
        for (int k = 0; k < 72; k += 4) {
            float x0 = a[k], x1 = a[k+1], x2 = a[k+2], x3 = a[k+3];
#pragma unroll
            for (int j = 0; j < 8; j++) {
                float4 wv = *(const float4*)&sw1[(oc + j) * 72 + k];
                acc[j] += wv.x * x0 + wv.y * x1 + wv.z * x2 + wv.w * x3;
            }
        }
#pragma unroll
        for (int j = 0; j < 8; j++) {
            float y = acc[j];
            act[(oc + j) * NT + tid] = fmaxf(y, 0.1f * y);
        }
    }

    float r[64];
#pragma unroll
    for (int k = 0; k < 64; k++) r[k] = act[k * NT + tid];

    // ---- layer 2: 64 -> 64 ----
#pragma unroll 1
    for (int oc = 0; oc < 64; oc += 8) {
        float acc[8];
#pragma unroll
        for (int j = 0; j < 8; j++) acc[j] = sb[64 + oc + j];
#pragma unroll
        for (int k = 0; k < 64; k += 4) {
            float x0 = r[k], x1 = r[k+1], x2 = r[k+2], x3 = r[k+3];
#pragma unroll
            for (int j = 0; j < 8; j++) {
                float4 wv = *(const float4*)&sw2[(oc + j) * 64 + k];
                acc[j] += wv.x * x0 + wv.y * x1 + wv.z * x2 + wv.w * x3;
            }
        }
#pragma unroll
        for (int j = 0; j < 8; j++) {
            float y = acc[j];
            act[(oc + j) * NT + tid] = fmaxf(y, 0.1f * y);
        }
    }
#pragma unroll
    for (int k = 0; k < 64; k++) r[k] = act[k * NT + tid];

    // ---- layer 3: 64 -> 64 ----
#pragma unroll 1
    for (int oc = 0; oc < 64; oc += 8) {
        float acc[8];
#pragma unroll
        for (int j = 0; j < 8; j++) acc[j] = sb[128 + oc + j];
#pragma unroll
        for (int k = 0; k < 64; k += 4) {
            float x0 = r[k], x1 = r[k+1], x2 = r[k+2], x3 = r[k+3];
#pragma unroll
            for (int j = 0; j < 8; j++) {
                float4 wv = *(const float4*)&sw3[(oc + j) * 64 + k];
                acc[j] += wv.x * x0 + wv.y * x1 + wv.z * x2 + wv.w * x3;
            }
        }
#pragma unroll
        for (int j = 0; j < 8; j++) {
            float y = acc[j];
            act[(oc + j) * NT + tid] = fmaxf(y, 0.1f * y);
        }
    }
#pragma unroll
    for (int k = 0; k < 64; k++) r[k] = act[k * NT + tid];

    // ---- layer 4: [x3 | feat2d] (128) -> 64, write out ----
    float* outp = out + (size_t)b * CC * HWSZ + pix;
#pragma unroll 1
    for (int oc = 0; oc < 64; oc += 8) {
        float acc[8];
#pragma unroll
        for (int j = 0; j < 8; j++) acc[j] = sb[192 + oc + j];
#pragma unroll
        for (int k = 0; k < 64; k += 4) {
            float x0 = r[k], x1 = r[k+1], x2 = r[k+2], x3 = r[k+3];
#pragma unroll
            for (int j = 0; j < 8; j++) {
                float4 wv = *(const float4*)&swf[(oc + j) * 128 + k];
                acc[j] += wv.x * x0 + wv.y * x1 + wv.z * x2 + wv.w * x3;
            }
        }
#pragma unroll
        for (int k = 0; k < 64; k += 4) {
            float x0 = f2b[(k+0) * NT + tid];
            float x1 = f2b[(k+1) * NT + tid];
            float x2 = f2b[(k+2) * NT + tid];
            float x3 = f2b[(k+3) * NT + tid];
#pragma unroll
            for (int j = 0; j < 8; j++) {
                float4 wv = *(const float4*)&swf[(oc + j) * 128 + 64 + k];
                acc[j] += wv.x * x0 + wv.y * x1 + wv.z * x2 + wv.w * x3;
            }
        }
#pragma unroll
        for (int j = 0; j < 8; j++) {
            float y = acc[j];
            outp[(size_t)(oc + j) * HWSZ] = fmaxf(y, 0.1f * y);
        }
    }
}

extern "C" void kernel_launch(void* const* d_in, const int* in_sizes, int n_in,
                              void* d_out, int out_size) {
    const float* xy    = (const float*)d_in[0];
    const float* f2d   = (const float*)d_in[1];
    const float* f3d   = (const float*)d_in[2];
    const float* lf2d  = (const float*)d_in[3];
    const float* lf3d  = (const float*)d_in[4];
    const int*   nnp   = (const int*)d_in[5];
    const float* w1 = (const float*)d_in[6];
    const float* b1 = (const float*)d_in[7];
    const float* w2 = (const float*)d_in[8];
    const float* b2 = (const float*)d_in[9];
    const float* w3 = (const float*)d_in[10];
    const float* b3 = (const float*)d_in[11];
    const float* wf = (const float*)d_in[12];
    const float* bf = (const float*)d_in[13];
    float* out = (float*)d_out;

    const int smem_bytes = SMEM_FLOATS * sizeof(float);   // ~211 KB
    cudaFuncSetAttribute(fused_kernel,
                         cudaFuncAttributeMaxDynamicSharedMemorySize, smem_bytes);

    prep_kernel<<<(BB * NPTS + 255) / 256, 256>>>(xy, f3d, lf3d);
    fused_kernel<<<(BB * HWSZ) / NT, NT, smem_bytes>>>(
        f2d, lf2d, nnp, w1, b1, w2, b2, w3, b3, wf, bf, out);
}

// round 5
// speedup vs baseline: 2.4228x; 2.4228x over previous
#include <cuda_runtime.h>
#include <cuda_bf16.h>
#include <cstdint>

#define BB 4
#define NPTS 16384
#define NT 128
#define NTILES 2048

// ---------------- global scratch ----------------
__device__ float g_T[BB * NPTS * 68];                 // per-point table
__device__ __align__(16) unsigned char g_W[94208];    // pre-split bf16 weights (hi+lo per layer)

// weight region offsets (bytes); 64 rows each, stride = odd*16B
#define BH1 0
#define BL1 11264
#define BH2 22528
#define BL2 31744
#define BH3 40960
#define BL3 50176
#define BH4 59392
#define BL4 76800
#define WBYTES 94208

// SMEM layout (bytes)
#define SM_B    0
#define SM_BIAS 94208      // 256 floats
#define SM_A1   95232      // 128 rows x 336B  (L1-L3 activations, hi|lo)
#define SM_A4   138240     // 128 rows x 528B  (L4 input: [x3|f2] hi | lo)
#define SMEM_TOTAL 205824

#define STRIDE_A1 336
#define STRIDE_A4 528

// ---------------- helpers ----------------
__device__ __forceinline__ uint32_t smem_u32(const void* p) {
    uint32_t a;
    asm("{ .reg .u64 t; cvta.to.shared.u64 t, %1; cvt.u32.u64 %0, t; }" : "=r"(a) : "l"(p));
    return a;
}

#define LDSM4(r0, r1, r2, r3, addr) \
    asm volatile("ldmatrix.sync.aligned.m8n8.x4.shared.b16 {%0,%1,%2,%3}, [%4];" \
                 : "=r"(r0), "=r"(r1), "=r"(r2), "=r"(r3) : "r"(addr))

#define MMA16816(c, a0, a1, a2, a3, b0, b1) \
    asm volatile("mma.sync.aligned.m16n8k16.row.col.f32.bf16.bf16.f32 " \
                 "{%0,%1,%2,%3}, {%4,%5,%6,%7}, {%8,%9}, {%0,%1,%2,%3};" \
                 : "+f"((c)[0]), "+f"((c)[1]), "+f"((c)[2]), "+f"((c)[3]) \
                 : "r"(a0), "r"(a1), "r"(a2), "r"(a3), "r"(b0), "r"(b1))

__device__ __forceinline__ uint32_t pack2(float x, float y) {
    unsigned short a = __bfloat16_as_ushort(__float2bfloat16_rn(x));
    unsigned short b = __bfloat16_as_ushort(__float2bfloat16_rn(y));
    return (uint32_t)a | ((uint32_t)b << 16);
}
__device__ __forceinline__ float lo_of(float x) {
    return x - __bfloat162float(__float2bfloat16_rn(x));
}
__device__ __forceinline__ float lrelu(float v) { return fmaxf(v, 0.1f * v); }

// ---------------- prep: transpose point table ----------------
__global__ void prep_kernel(const float* __restrict__ xy,
                            const float* __restrict__ feat3d,
                            const float* __restrict__ flow3d) {
    int gp = blockIdx.x * blockDim.x + threadIdx.x;
    if (gp >= BB * NPTS) return;
    int b = gp >> 14;
    int p = gp & (NPTS - 1);
    float* dst = g_T + (size_t)gp * 68;
    const float* src = feat3d + (size_t)b * 64 * NPTS + p;
#pragma unroll
    for (int c = 0; c < 64; c++) dst[c] = src[c * NPTS];
    dst[64] = flow3d[((size_t)b * 2 + 0) * NPTS + p];
    dst[65] = flow3d[((size_t)b * 2 + 1) * NPTS + p];
    dst[66] = xy[((size_t)b * 2 + 0) * NPTS + p];
    dst[67] = xy[((size_t)b * 2 + 1) * NPTS + p];
}

// ---------------- prep: split weights into hi/lo bf16 rows ----------------
__global__ void wprep_kernel(const float* __restrict__ w1, const float* __restrict__ w2,
                             const float* __restrict__ w3, const float* __restrict__ wf) {
    int i = blockIdx.x * 256 + threadIdx.x;   // n*368 + c
    if (i >= 64 * 368) return;
    int n = i / 368;
    int c = i - n * 368;
    int l, k;
    if (c < 88)       { l = 0; k = c; }
    else if (c < 160) { l = 1; k = c - 88; }
    else if (c < 232) { l = 2; k = c - 160; }
    else              { l = 3; k = c - 232; }
    const int KR[4]    = {69, 64, 64, 128};
    const int STR[4]   = {176, 144, 144, 272};
    const int BH[4]    = {BH1, BH2, BH3, BH4};
    const int BL[4]    = {BL1, BL2, BL3, BL4};
    const float* src = (l == 0) ? w1 : (l == 1) ? w2 : (l == 2) ? w3 : wf;
    float v = (k < KR[l]) ? src[n * KR[l] + k] : 0.0f;
    float hf = __bfloat162float(__float2bfloat16_rn(v));
    unsigned short hb = __bfloat16_as_ushort(__float2bfloat16_rn(v));
    unsigned short lb = __bfloat16_as_ushort(__float2bfloat16_rn(v - hf));
    int off = n * STR[l] + k * 2;
    *(unsigned short*)(g_W + BH[l] + off) = hb;
    *(unsigned short*)(g_W + BL[l] + off) = lb;
}

// ---------------- per-warp GEMM layer ----------------
// acc[64] += A[32 x K'] * B[K' x 64], 3 segments: (A-hi,B-hi),(A-lo,B-hi),(A-hi,B-lo)
__device__ __forceinline__ void run_layer(float* acc, uint32_t aBase, int strideA,
                                          int loOffB, int ksegs,
                                          uint32_t bHi, uint32_t bLo, int strideB,
                                          int lane, int warpPix) {
    const int g = lane >> 3, r = lane & 7;
    const int aRow  = ((g & 1) << 3) + r;
    const int aColB = (g >> 1) << 4;
    const int bRow  = ((g >> 1) << 3) + r;
    const int bColB = (g & 1) << 4;
    const uint32_t aRowAddr = aBase + (uint32_t)(warpPix + aRow) * strideA + aColB;

#pragma unroll
    for (int s = 0; s < 3; s++) {
        const uint32_t aoff = (s == 1) ? (uint32_t)loOffB : 0u;
        const uint32_t bb = ((s == 2) ? bLo : bHi) + (uint32_t)bRow * strideB + bColB;
#pragma unroll
        for (int j = 0; j < ksegs; j++) {
            uint32_t A0[4], A1[4], Bq[4][4];
            uint32_t addrA = aRowAddr + aoff + (uint32_t)(j << 5);
            LDSM4(A0[0], A0[1], A0[2], A0[3], addrA);
            LDSM4(A1[0], A1[1], A1[2], A1[3], addrA + 16u * strideA);
#pragma unroll
            for (int q = 0; q < 4; q++) {
                uint32_t addrB = bb + (uint32_t)(q << 4) * strideB + (uint32_t)(j << 5);
                LDSM4(Bq[q][0], Bq[q][1], Bq[q][2], Bq[q][3], addrB);
            }
#pragma unroll
            for (int nt = 0; nt < 8; nt++) {
                uint32_t b0 = Bq[nt >> 1][(nt & 1) << 1];
                uint32_t b1 = Bq[nt >> 1][((nt & 1) << 1) + 1];
                MMA16816(acc + nt * 4,       A0[0], A0[1], A0[2], A0[3], b0, b1);
                MMA16816(acc + 32 + nt * 4,  A1[0], A1[1], A1[2], A1[3], b0, b1);
            }
        }
    }
}

// epilogue: bias + lrelu + split-bf16 store into next A tile (own-warp rows only)
__device__ __forceinline__ void epi_store(const float* acc, const float* bias,
                                          char* dst, int strideA, int loOffB,
                                          int lane, int warpPix) {
    const int r = lane >> 2;
    const int nb = (lane & 3) << 1;
#pragma unroll
    for (int mt = 0; mt < 2; mt++) {
        const int row0 = warpPix + (mt << 4) + r;
        char* p0 = dst + row0 * strideA;
        char* p1 = p0 + 8 * strideA;
#pragma unroll
        for (int nt = 0; nt < 8; nt++) {
            const float* c = acc + mt * 32 + nt * 4;
            const int n = (nt << 3) + nb;
            float b0 = bias[n], b1 = bias[n + 1];
            float v00 = lrelu(c[0] + b0), v01 = lrelu(c[1] + b1);
            float v10 = lrelu(c[2] + b0), v11 = lrelu(c[3] + b1);
            *(uint32_t*)(p0 + n * 2)          = pack2(v00, v01);
            *(uint32_t*)(p0 + loOffB + n * 2) = pack2(lo_of(v00), lo_of(v01));
            *(uint32_t*)(p1 + n * 2)          = pack2(v10, v11);
            *(uint32_t*)(p1 + loOffB + n * 2) = pack2(lo_of(v10), lo_of(v11));
        }
    }
}

// ---------------- fused kernel ----------------
__global__ __launch_bounds__(NT, 1)
void fused_kernel(const float* __restrict__ feat2d,
                  const float* __restrict__ lf2d,
                  const int*   __restrict__ nnp,
                  const float* __restrict__ b1, const float* __restrict__ b2,
                  const float* __restrict__ b3, const float* __restrict__ bfin,
                  float* __restrict__ out) {
    extern __shared__ char smem[];
    const uint32_t s32 = smem_u32(smem);
    const int tid  = threadIdx.x;
    const int lane = tid & 31;
    const int warpPix = tid & 96;          // (tid/32)*32

    // ---- one-time: weights + bias into SMEM ----
    {
        const uint4* src = (const uint4*)g_W;
        uint4* dst = (uint4*)(smem + SM_B);
        for (int i = tid; i < WBYTES / 16; i += NT) dst[i] = src[i];
        float* sb = (float*)(smem + SM_BIAS);
        if (tid < 64) {
            sb[tid]       = b1[tid];
            sb[64 + tid]  = b2[tid];
            sb[128 + tid] = b3[tid];
            sb[192 + tid] = bfin[tid];
        }
    }
    __syncthreads();
    const float* sbias = (const float*)(smem + SM_BIAS);

    for (int tile = blockIdx.x; tile < NTILES; tile += gridDim.x) {
        const int gp  = (tile << 7) + tid;
        const int b   = gp >> 16;
        const int pix = gp & 65535;

        // ---------- prologue (thread = pixel; writes ONLY row tid) ----------
        {
            const int wi  = pix & 255;
            const int hi_ = pix >> 8;
            const int idx = nnp[gp];
            const float* t3 = g_T + (size_t)((b << 14) + idx) * 68;

            float a[80];
#pragma unroll
            for (int k = 0; k < 64; k += 4) {
                float4 v = *(const float4*)(t3 + k);
                a[3 + k] = v.x; a[4 + k] = v.y; a[5 + k] = v.z; a[6 + k] = v.w;
            }
            {
                float4 tv = *(const float4*)(t3 + 64);
                a[1] = tv.z - (float)wi;
                a[2] = tv.w - (float)hi_;
                const float* lf = lf2d + (((size_t)b * 2) << 16) + pix;
                a[67] = tv.x - lf[0];
                a[68] = tv.y - lf[65536];
            }
#pragma unroll
            for (int k = 69; k < 80; k++) a[k] = 0.0f;

            // corr + feat2d -> L4 A tile (cols 64..127 hi, 192..255 lo)
            char* A4p = smem + SM_A4 + tid * STRIDE_A4;
            {
                const float* f2p = feat2d + (((size_t)b * 64) << 16) + pix;
                float corr = 0.0f;
#pragma unroll
                for (int c = 0; c < 64; c += 2) {
                    float v0 = f2p[(size_t)c << 16];
                    float v1 = f2p[(size_t)(c + 1) << 16];
                    corr += a[3 + c] * v0 + a[4 + c] * v1;
                    *(uint32_t*)(A4p + (64 + c) * 2)  = pack2(v0, v1);
                    *(uint32_t*)(A4p + (192 + c) * 2) = pack2(lo_of(v0), lo_of(v1));
                }
                a[0] = corr * (1.0f / 64.0f);
            }

            // L1 A tile: hi cols 0..79, lo cols 80..159
            char* A1p = smem + SM_A1 + tid * STRIDE_A1;
#pragma unroll
            for (int k = 0; k < 80; k += 2) {
                *(uint32_t*)(A1p + k * 2)         = pack2(a[k], a[k + 1]);
                *(uint32_t*)(A1p + 160 + k * 2)   = pack2(lo_of(a[k]), lo_of(a[k + 1]));
            }
        }
        __syncwarp();

        float acc[64];

        // ---- layer 1: K=80 ----
#pragma unroll
        for (int i = 0; i < 64; i++) acc[i] = 0.0f;
        run_layer(acc, s32 + SM_A1, STRIDE_A1, 160, 5,
                  s32 + SM_B + BH1, s32 + SM_B + BL1, 176, lane, warpPix);
        epi_store(acc, sbias, smem + SM_A1, STRIDE_A1, 128, lane, warpPix);
        __syncwarp();

        // ---- layer 2 ----
#pragma unroll
        for (int i = 0; i < 64; i++) acc[i] = 0.0f;
        run_layer(acc, s32 + SM_A1, STRIDE_A1, 128, 4,
                  s32 + SM_B + BH2, s32 + SM_B + BL2, 144, lane, warpPix);
        epi_store(acc, sbias + 64, smem + SM_A1, STRIDE_A1, 128, lane, warpPix);
        __syncwarp();

        // ---- layer 3 -> writes x3 into L4 A tile (hi 0..63, lo 128..191) ----
#pragma unroll
        for (int i = 0; i < 64; i++) acc[i] = 0.0f;
        run_layer(acc, s32 + SM_A1, STRIDE_A1, 128, 4,
                  s32 + SM_B + BH3, s32 + SM_B + BL3, 144, lane, warpPix);
        epi_store(acc, sbias + 128, smem + SM_A4, STRIDE_A4, 256, lane, warpPix);
        __syncwarp();

        // ---- layer 4: K=128 ----
#pragma unroll
        for (int i = 0; i < 64; i++) acc[i] = 0.0f;
        run_layer(acc, s32 + SM_A4, STRIDE_A4, 256, 8,
                  s32 + SM_B + BH4, s32 + SM_B + BL4, 272, lane, warpPix);

        // ---- output epilogue: DIRECT STG from fragments (no SMEM staging) ----
        // Per STG.32: 32 lanes hit 4 channel planes x 8 consecutive pixels = 4 full sectors.
        {
            const int pixbase = (tile << 7) & 65535;
            const int r = lane >> 2;
            const int nb = (lane & 3) << 1;
            float* ob = out + ((size_t)b << 22) + pixbase;
#pragma unroll
            for (int mt = 0; mt < 2; mt++) {
                float* p0 = ob + warpPix + (mt << 4) + r;
                float* p1 = p0 + 8;
#pragma unroll
                for (int nt = 0; nt < 8; nt++) {
                    const float* c = acc + mt * 32 + nt * 4;
                    const int n = (nt << 3) + nb;
                    float bb0 = sbias[192 + n], bb1 = sbias[192 + n + 1];
                    p0[(size_t)n << 16]       = lrelu(c[0] + bb0);
                    p0[(size_t)(n + 1) << 16] = lrelu(c[1] + bb1);
                    p1[(size_t)n << 16]       = lrelu(c[2] + bb0);
                    p1[(size_t)(n + 1) << 16] = lrelu(c[3] + bb1);
                }
            }
        }
        __syncwarp();   // own-warp A tiles safe before next prologue overwrites
    }
}

extern "C" void kernel_launch(void* const* d_in, const int* in_sizes, int n_in,
                              void* d_out, int out_size) {
    const float* xy    = (const float*)d_in[0];
    const float* f2d   = (const float*)d_in[1];
    const float* f3d   = (const float*)d_in[2];
    const float* lf2d  = (const float*)d_in[3];
    const float* lf3d  = (const float*)d_in[4];
    const int*   nnp   = (const int*)d_in[5];
    const float* w1 = (const float*)d_in[6];
    const float* b1 = (const float*)d_in[7];
    const float* w2 = (const float*)d_in[8];
    const float* b2 = (const float*)d_in[9];
    const float* w3 = (const float*)d_in[10];
    const float* b3 = (const float*)d_in[11];
    const float* wf = (const float*)d_in[12];
    const float* bf = (const float*)d_in[13];
    float* out = (float*)d_out;

    cudaFuncSetAttribute(fused_kernel,
                         cudaFuncAttributeMaxDynamicSharedMemorySize, SMEM_TOTAL);

    prep_kernel<<<(BB * NPTS + 255) / 256, 256>>>(xy, f3d, lf3d);
    wprep_kernel<<<(64 * 368 + 255) / 256, 256>>>(w1, w2, w3, wf);
    fused_kernel<<<148, NT, SMEM_TOTAL>>>(f2d, lf2d, nnp, b1, b2, b3, bf, out);
}

// round 7
// speedup vs baseline: 3.0133x; 1.2437x over previous
#include <cuda_runtime.h>
#include <cuda_bf16.h>
#include <cstdint>

#define BB 4
#define NPTS 16384
#define NT 256
#define NTILES 2048

// ---------------- global scratch ----------------
__device__ float g_T[BB * NPTS * 68];                 // per-point table
__device__ __align__(16) unsigned char g_W[94208];    // pre-split bf16 weights (hi+lo per layer)

// weight region offsets (bytes); 64 rows each, stride = odd*16B
#define BH1 0
#define BL1 11264
#define BH2 22528
#define BL2 31744
#define BH3 40960
#define BL3 50176
#define BH4 59392
#define BL4 76800
#define WBYTES 94208

// SMEM layout (bytes)
#define SM_B    0
#define SM_BIAS 94208      // 256 floats
#define SM_A1   95232      // 128 rows x 336B  (L1-L3 activations, hi|lo)
#define SM_A4   138240     // 128 rows x 528B  (L4 input: [x3|f2] hi | lo)
#define SM_SCR  205824     // 256 floats corr partials
#define SMEM_TOTAL 206848

#define STRIDE_A1 336
#define STRIDE_A4 528

// ---------------- helpers ----------------
__device__ __forceinline__ uint32_t smem_u32(const void* p) {
    uint32_t a;
    asm("{ .reg .u64 t; cvta.to.shared.u64 t, %1; cvt.u32.u64 %0, t; }" : "=r"(a) : "l"(p));
    return a;
}

#define LDSM4(r0, r1, r2, r3, addr) \
    asm volatile("ldmatrix.sync.aligned.m8n8.x4.shared.b16 {%0,%1,%2,%3}, [%4];" \
                 : "=r"(r0), "=r"(r1), "=r"(r2), "=r"(r3) : "r"(addr))

#define MMA16816(c, a0, a1, a2, a3, b0, b1) \
    asm volatile("mma.sync.aligned.m16n8k16.row.col.f32.bf16.bf16.f32 " \
                 "{%0,%1,%2,%3}, {%4,%5,%6,%7}, {%8,%9}, {%0,%1,%2,%3};" \
                 : "+f"((c)[0]), "+f"((c)[1]), "+f"((c)[2]), "+f"((c)[3]) \
                 : "r"(a0), "r"(a1), "r"(a2), "r"(a3), "r"(b0), "r"(b1))

__device__ __forceinline__ uint32_t pack2(float x, float y) {
    unsigned short a = __bfloat16_as_ushort(__float2bfloat16_rn(x));
    unsigned short b = __bfloat16_as_ushort(__float2bfloat16_rn(y));
    return (uint32_t)a | ((uint32_t)b << 16);
}
__device__ __forceinline__ float lo_of(float x) {
    return x - __bfloat162float(__float2bfloat16_rn(x));
}
__device__ __forceinline__ float lrelu(float v) { return fmaxf(v, 0.1f * v); }

// ---------------- prep (smem-transpose, coalesced) + wprep merged ----------------
__global__ void prep_kernel(const float* __restrict__ xy,
                            const float* __restrict__ feat3d,
                            const float* __restrict__ flow3d,
                            const float* __restrict__ w1, const float* __restrict__ w2,
                            const float* __restrict__ w3, const float* __restrict__ wf) {
    const int blk = blockIdx.x;
    const int tid = threadIdx.x;
    if (blk < 1024) {
        // ---- point-table transpose: block = 64 points of one batch ----
        __shared__ float sT[68 * 67];
        const int b  = blk >> 8;
        const int p0 = (blk & 255) << 6;
        const float* f3 = feat3d + (size_t)b * 64 * NPTS + p0;
#pragma unroll
        for (int it = 0; it < 16; it++) {
            int i = it * 256 + tid;
            int c = i >> 6, pt = i & 63;
            sT[c * 67 + pt] = f3[(size_t)c * NPTS + pt];
        }
        if (tid < 128) {
            int c = tid >> 6, pt = tid & 63;
            sT[(64 + c) * 67 + pt] = flow3d[((size_t)b * 2 + c) * NPTS + p0 + pt];
            sT[(66 + c) * 67 + pt] = xy[((size_t)b * 2 + c) * NPTS + p0 + pt];
        }
        __syncthreads();
        float* dst = g_T + ((size_t)(b << 14) + p0) * 68;
#pragma unroll
        for (int it = 0; it < 17; it++) {
            int i = it * 256 + tid;
            int pt = i / 68;                // exact; compiler emits correct magic
            int c = i - pt * 68;
            dst[i] = sT[c * 67 + pt];
        }
    } else {
        // ---- weight split (hi/lo bf16) ----
        int i = (blk - 1024) * 256 + tid;   // 0..23551 = n*368 + c
        int n = i / 368;
        int c = i - n * 368;
        int l, k;
        if (c < 88)       { l = 0; k = c; }
        else if (c < 160) { l = 1; k = c - 88; }
        else if (c < 232) { l = 2; k = c - 160; }
        else              { l = 3; k = c - 232; }
        const int KR[4]  = {69, 64, 64, 128};
        const int STR[4] = {176, 144, 144, 272};
        const int BH[4]  = {BH1, BH2, BH3, BH4};
        const int BL[4]  = {BL1, BL2, BL3, BL4};
        const float* src = (l == 0) ? w1 : (l == 1) ? w2 : (l == 2) ? w3 : wf;
        float v = (k < KR[l]) ? src[n * KR[l] + k] : 0.0f;
        // L1 column remap: activations place feat at cols 4..67 (pad col 3)
        int col = (l == 0) ? ((k < 3) ? k : k + 1) : k;
        float hf = __bfloat162float(__float2bfloat16_rn(v));
        unsigned short hb = __bfloat16_as_ushort(__float2bfloat16_rn(v));
        unsigned short lb = __bfloat16_as_ushort(__float2bfloat16_rn(v - hf));
        if (col * 2 < STR[l]) {
            int off = n * STR[l] + col * 2;
            *(unsigned short*)(g_W + BH[l] + off) = hb;
            *(unsigned short*)(g_W + BL[l] + off) = lb;
        }
        if (l == 0 && k == 87) {            // cover padded col 3
            int off = n * 176 + 3 * 2;
            *(unsigned short*)(g_W + BH1 + off) = 0;
            *(unsigned short*)(g_W + BL1 + off) = 0;
        }
    }
}

// ---------------- per-warp GEMM layer (N-split, B-hi reuse) ----------------
// acc[32] += A[32px x K'] * B[K' x 32], segments fused per j: hh + lh + hl
__device__ __forceinline__ void run_layer(float* acc, uint32_t aBase, int strideA,
                                          int loAoff, int ksegs,
                                          uint32_t bHi, uint32_t bLo, int strideB,
                                          int lane, int warpPix, int nBase) {
    const int g = lane >> 3, r = lane & 7;
    const int aRow  = ((g & 1) << 3) + r;
    const int aColB = (g >> 1) << 4;
    const int bRow  = ((g >> 1) << 3) + r;
    const int bColB = (g & 1) << 4;
    const uint32_t aAddr = aBase + (uint32_t)(warpPix + aRow) * strideA + aColB;
    const uint32_t bhAddr = bHi + (uint32_t)(nBase + bRow) * strideB + bColB;
    const uint32_t blAddr = bLo + (uint32_t)(nBase + bRow) * strideB + bColB;

#pragma unroll
    for (int j = 0; j < ksegs; j++) {
        const uint32_t ja = (uint32_t)(j << 5);
        uint32_t Ah0[4], Ah1[4], Al0[4], Al1[4], Bh[2][4], Bl[2][4];
        LDSM4(Ah0[0], Ah0[1], Ah0[2], Ah0[3], aAddr + ja);
        LDSM4(Ah1[0], Ah1[1], Ah1[2], Ah1[3], aAddr + ja + 16u * strideA);
        LDSM4(Al0[0], Al0[1], Al0[2], Al0[3], aAddr + ja + loAoff);
        LDSM4(Al1[0], Al1[1], Al1[2], Al1[3], aAddr + ja + loAoff + 16u * strideA);
        LDSM4(Bh[0][0], Bh[0][1], Bh[0][2], Bh[0][3], bhAddr + ja);
        LDSM4(Bh[1][0], Bh[1][1], Bh[1][2], Bh[1][3], bhAddr + ja + 16u * strideB);
        LDSM4(Bl[0][0], Bl[0][1], Bl[0][2], Bl[0][3], blAddr + ja);
        LDSM4(Bl[1][0], Bl[1][1], Bl[1][2], Bl[1][3], blAddr + ja + 16u * strideB);
#pragma unroll
        for (int nt = 0; nt < 4; nt++) {
            const int q = nt >> 1, ix = (nt & 1) << 1;
            uint32_t bh0 = Bh[q][ix], bh1 = Bh[q][ix + 1];
            uint32_t bl0 = Bl[q][ix], bl1 = Bl[q][ix + 1];
            float* c0 = acc + nt * 4;
            float* c1 = acc + 16 + nt * 4;
            MMA16816(c0, Ah0[0], Ah0[1], Ah0[2], Ah0[3], bh0, bh1);
            MMA16816(c1, Ah1[0], Ah1[1], Ah1[2], Ah1[3], bh0, bh1);
            MMA16816(c0, Al0[0], Al0[1], Al0[2], Al0[3], bh0, bh1);
            MMA16816(c1, Al1[0], Al1[1], Al1[2], Al1[3], bh0, bh1);
            MMA16816(c0, Ah0[0], Ah0[1], Ah0[2], Ah0[3], bl0, bl1);
            MMA16816(c1, Ah1[0], Ah1[1], Ah1[2], Ah1[3], bl0, bl1);
        }
    }
}

// epilogue: bias + lrelu + split-bf16 store into next A tile (N-half columns)
__device__ __forceinline__ void epi_store(const float* acc, const float* bias,
                                          char* dst, int strideA, int loOffB,
                                          int lane, int warpPix, int nBase) {
    const int r = lane >> 2;
    const int nb = (lane & 3) << 1;
#pragma unroll
    for (int mt = 0; mt < 2; mt++) {
        char* p0 = dst + (warpPix + (mt << 4) + r) * strideA;
        char* p1 = p0 + 8 * strideA;
#pragma unroll
        for (int nt = 0; nt < 4; nt++) {
            const float* c = acc + mt * 16 + nt * 4;
            const int n = nBase + (nt << 3) + nb;
            float b0 = bias[n], b1 = bias[n + 1];
            float v00 = lrelu(c[0] + b0), v01 = lrelu(c[1] + b1);
            float v10 = lrelu(c[2] + b0), v11 = lrelu(c[3] + b1);
            *(uint32_t*)(p0 + n * 2)          = pack2(v00, v01);
            *(uint32_t*)(p0 + loOffB + n * 2) = pack2(lo_of(v00), lo_of(v01));
            *(uint32_t*)(p1 + n * 2)          = pack2(v10, v11);
            *(uint32_t*)(p1 + loOffB + n * 2) = pack2(lo_of(v10), lo_of(v11));
        }
    }
}

// ---------------- fused kernel ----------------
__global__ __launch_bounds__(NT, 1)
void fused_kernel(const float* __restrict__ feat2d,
                  const float* __restrict__ lf2d,
                  const int*   __restrict__ nnp,
                  const float* __restrict__ b1, const float* __restrict__ b2,
                  const float* __restrict__ b3, const float* __restrict__ bfin,
                  float* __restrict__ out) {
    extern __shared__ char smem[];
    const uint32_t s32 = smem_u32(smem);
    const int tid  = threadIdx.x;
    const int lane = tid & 31;
    const int wid  = tid >> 5;
    const int warpPix = (wid >> 1) << 5;   // pixel-group base (0,32,64,96)
    const int nBase   = (wid & 1) << 5;    // N-half (0 or 32)
    const int pl   = tid & 127;            // prologue pixel
    const int half = tid >> 7;             // prologue channel half

    // ---- one-time: weights + bias into SMEM ----
    {
        const uint4* src = (const uint4*)g_W;
        uint4* dst = (uint4*)(smem + SM_B);
        for (int i = tid; i < WBYTES / 16; i += NT) dst[i] = src[i];
        float* sb = (float*)(smem + SM_BIAS);
        if (tid < 64) {
            sb[tid]       = b1[tid];
            sb[64 + tid]  = b2[tid];
            sb[128 + tid] = b3[tid];
            sb[192 + tid] = bfin[tid];
        }
    }
    __syncthreads();
    const float* sbias = (const float*)(smem + SM_BIAS);
    float* scr = (float*)(smem + SM_SCR);

    for (int tile = blockIdx.x; tile < NTILES; tile += gridDim.x) {
        const int gp  = (tile << 7) + pl;
        const int b   = gp >> 16;
        const int pix = gp & 65535;

        // ---------- prologue: thread (pl, half) = pixel pl, channels [32h,32h+32) ----
        {
            const int idx = nnp[gp];
            const float* t3 = g_T + (size_t)((b << 14) + idx) * 68;
            float av[32];
            const float* t3h = t3 + (half << 5);
#pragma unroll
            for (int k = 0; k < 32; k += 4) {
                float4 v = *(const float4*)(t3h + k);
                av[k] = v.x; av[k + 1] = v.y; av[k + 2] = v.z; av[k + 3] = v.w;
            }
            // half1 extras loaded early to overlap latency
            float4 tv = make_float4(0.f, 0.f, 0.f, 0.f);
            float lfx = 0.f, lfy = 0.f;
            if (half) {
                tv = *(const float4*)(t3 + 64);        // fl0, fl1, xyx, xyy
                const float* lf = lf2d + (((size_t)b * 2) << 16) + pix;
                lfx = lf[0]; lfy = lf[65536];
            }

            // f2 half + partial corr + A4 f2 cols
            char* A4p = smem + SM_A4 + pl * STRIDE_A4;
            const float* f2p = feat2d + (((size_t)(b * 64 + (half << 5))) << 16) + pix;
            float pc = 0.0f;
#pragma unroll
            for (int c = 0; c < 32; c += 2) {
                float v0 = f2p[(size_t)c << 16];
                float v1 = f2p[(size_t)(c + 1) << 16];
                pc += av[c] * v0 + av[c + 1] * v1;
                *(uint32_t*)(A4p + 128 + (half << 6) + c * 2) = pack2(v0, v1);
                *(uint32_t*)(A4p + 384 + (half << 6) + c * 2) = pack2(lo_of(v0), lo_of(v1));
            }
            // A1 feat cols 4+32h.. (hi) / +160B (lo)
            char* A1p = smem + SM_A1 + pl * STRIDE_A1;
#pragma unroll
            for (int k = 0; k < 32; k += 2) {
                int cb = (4 + (half << 5) + k) * 2;
                *(uint32_t*)(A1p + cb)       = pack2(av[k], av[k + 1]);
                *(uint32_t*)(A1p + 160 + cb) = pack2(lo_of(av[k]), lo_of(av[k + 1]));
            }
            scr[tid] = pc;
            __syncthreads();
            if (half) {
                float corr = (scr[pl] + scr[pl + 128]) * (1.0f / 64.0f);
                float offx = tv.z - (float)(pix & 255);
                float offy = tv.w - (float)(pix >> 8);
                float fl0 = tv.x - lfx, fl1 = tv.y - lfy;
                *(uint32_t*)(A1p + 0)   = pack2(corr, offx);
                *(uint32_t*)(A1p + 4)   = pack2(offy, 0.0f);
                *(uint32_t*)(A1p + 160) = pack2(lo_of(corr), lo_of(offx));
                *(uint32_t*)(A1p + 164) = pack2(lo_of(offy), 0.0f);
                *(uint32_t*)(A1p + 136) = pack2(fl0, fl1);          // cols 68,69
                *(uint32_t*)(A1p + 296) = pack2(lo_of(fl0), lo_of(fl1));
#pragma unroll
                for (int z = 0; z < 5; z++) {                        // cols 70..79 zero
                    *(uint32_t*)(A1p + 140 + z * 4) = 0u;
                    *(uint32_t*)(A1p + 300 + z * 4) = 0u;
                }
            }
        }
        __syncthreads();

        float acc[32];

        // ---- layer 1: K=80 ----
#pragma unroll
        for (int i = 0; i < 32; i++) acc[i] = 0.0f;
        run_layer(acc, s32 + SM_A1, STRIDE_A1, 160, 5,
                  s32 + SM_B + BH1, s32 + SM_B + BL1, 176, lane, warpPix, nBase);
        epi_store(acc, sbias, smem + SM_A1, STRIDE_A1, 128, lane, warpPix, nBase);
        __syncthreads();

        // ---- layer 2 ----
#pragma unroll
        for (int i = 0; i < 32; i++) acc[i] = 0.0f;
        run_layer(acc, s32 + SM_A1, STRIDE_A1, 128, 4,
                  s32 + SM_B + BH2, s32 + SM_B + BL2, 144, lane, warpPix, nBase);
        epi_store(acc, sbias + 64, smem + SM_A1, STRIDE_A1, 128, lane, warpPix, nBase);
        __syncthreads();

        // ---- layer 3 -> x3 into L4 A tile (hi 0..63, lo @ +256B) ----
#pragma unroll
        for (int i = 0; i < 32; i++) acc[i] = 0.0f;
        run_layer(acc, s32 + SM_A1, STRIDE_A1, 128, 4,
                  s32 + SM_B + BH3, s32 + SM_B + BL3, 144, lane, warpPix, nBase);
        epi_store(acc, sbias + 128, smem + SM_A4, STRIDE_A4, 256, lane, warpPix, nBase);
        __syncthreads();

        // ---- layer 4: K=128 ----
#pragma unroll
        for (int i = 0; i < 32; i++) acc[i] = 0.0f;
        run_layer(acc, s32 + SM_A4, STRIDE_A4, 256, 8,
                  s32 + SM_B + BH4, s32 + SM_B + BL4, 272, lane, warpPix, nBase);

        // ---- output: direct STG from fragments ----
        {
            const int pixbase = (tile << 7) & 65535;
            const int r = lane >> 2;
            const int nb = (lane & 3) << 1;
            float* ob = out + ((size_t)b << 22) + pixbase;
#pragma unroll
            for (int mt = 0; mt < 2; mt++) {
                float* p0 = ob + warpPix + (mt << 4) + r;
                float* p1 = p0 + 8;
#pragma unroll
                for (int nt = 0; nt < 4; nt++) {
                    const float* c = acc + mt * 16 + nt * 4;
                    const int n = nBase + (nt << 3) + nb;
                    float bb0 = sbias[192 + n], bb1 = sbias[192 + n + 1];
                    p0[(size_t)n << 16]       = lrelu(c[0] + bb0);
                    p0[(size_t)(n + 1) << 16] = lrelu(c[1] + bb1);
                    p1[(size_t)n << 16]       = lrelu(c[2] + bb0);
                    p1[(size_t)(n + 1) << 16] = lrelu(c[3] + bb1);
                }
            }
        }
        __syncthreads();   // A tiles fully consumed before next prologue
    }
}

extern "C" void kernel_launch(void* const* d_in, const int* in_sizes, int n_in,
                              void* d_out, int out_size) {
    const float* xy    = (const float*)d_in[0];
    const float* f2d   = (const float*)d_in[1];
    const float* f3d   = (const float*)d_in[2];
    const float* lf2d  = (const float*)d_in[3];
    const float* lf3d  = (const float*)d_in[4];
    const int*   nnp   = (const int*)d_in[5];
    const float* w1 = (const float*)d_in[6];
    const float* b1 = (const float*)d_in[7];
    const float* w2 = (const float*)d_in[8];
    const float* b2 = (const float*)d_in[9];
    const float* w3 = (const float*)d_in[10];
    const float* b3 = (const float*)d_in[11];
    const float* wf = (const float*)d_in[12];
    const float* bf = (const float*)d_in[13];
    float* out = (float*)d_out;

    cudaFuncSetAttribute(fused_kernel,
                         cudaFuncAttributeMaxDynamicSharedMemorySize, SMEM_TOTAL);

    prep_kernel<<<1024 + 92, 256>>>(xy, f3d, lf3d, w1, w2, w3, wf);
    fused_kernel<<<148, NT, SMEM_TOTAL>>>(f2d, lf2d, nnp, b1, b2, b3, bf, out);
}

// round 9
// speedup vs baseline: 3.6454x; 1.2098x over previous
#include <cuda_runtime.h>
#include <cuda_bf16.h>
#include <cstdint>

#define BB 4
#define NPTS 16384
#define NT 512
#define NTILES 2048

// ---------------- global scratch ----------------
__device__ float g_T[BB * NPTS * 68];                 // per-point table
__device__ __align__(16) unsigned char g_W[94208];    // pre-split bf16 weights (hi+lo per layer)

// weight region offsets (bytes); 64 rows each, stride = odd*16B
#define BH1 0
#define BL1 11264
#define BH2 22528
#define BL2 31744
#define BH3 40960
#define BL3 50176
#define BH4 59392
#define BL4 76800
#define WBYTES 94208

// SMEM layout (bytes)
#define SM_B    0
#define SM_BIAS 94208      // 256 floats
#define SM_A1   95232      // 128 rows x 336B  (L1-L3 activations, hi|lo)
#define SM_A4   138240     // 128 rows x 528B  (L4 input: [x3|f2] hi | lo)
#define SM_SCR  205824     // 512 floats corr partials
#define SMEM_TOTAL 207872

#define STRIDE_A1 336
#define STRIDE_A4 528

// ---------------- helpers ----------------
__device__ __forceinline__ uint32_t smem_u32(const void* p) {
    uint32_t a;
    asm("{ .reg .u64 t; cvta.to.shared.u64 t, %1; cvt.u32.u64 %0, t; }" : "=r"(a) : "l"(p));
    return a;
}

#define GBAR(id) asm volatile("bar.sync %0, 128;" :: "r"(id) : "memory")

#define LDSM4(r0, r1, r2, r3, addr) \
    asm volatile("ldmatrix.sync.aligned.m8n8.x4.shared.b16 {%0,%1,%2,%3}, [%4];" \
                 : "=r"(r0), "=r"(r1), "=r"(r2), "=r"(r3) : "r"(addr))

#define MMA16816(c, a0, a1, a2, a3, b0, b1) \
    asm volatile("mma.sync.aligned.m16n8k16.row.col.f32.bf16.bf16.f32 " \
                 "{%0,%1,%2,%3}, {%4,%5,%6,%7}, {%8,%9}, {%0,%1,%2,%3};" \
                 : "+f"((c)[0]), "+f"((c)[1]), "+f"((c)[2]), "+f"((c)[3]) \
                 : "r"(a0), "r"(a1), "r"(a2), "r"(a3), "r"(b0), "r"(b1))

__device__ __forceinline__ uint32_t pack2(float x, float y) {
    unsigned short a = __bfloat16_as_ushort(__float2bfloat16_rn(x));
    unsigned short b = __bfloat16_as_ushort(__float2bfloat16_rn(y));
    return (uint32_t)a | ((uint32_t)b << 16);
}
__device__ __forceinline__ float lo_of(float x) {
    return x - __bfloat162float(__float2bfloat16_rn(x));
}
__device__ __forceinline__ float lrelu(float v) { return fmaxf(v, 0.1f * v); }

// ---------------- prep (smem-transpose, coalesced) + wprep merged ----------------
__global__ void prep_kernel(const float* __restrict__ xy,
                            const float* __restrict__ feat3d,
                            const float* __restrict__ flow3d,
                            const float* __restrict__ w1, const float* __restrict__ w2,
                            const float* __restrict__ w3, const float* __restrict__ wf) {
    const int blk = blockIdx.x;
    const int tid = threadIdx.x;
    if (blk < 1024) {
        __shared__ float sT[68 * 67];
        const int b  = blk >> 8;
        const int p0 = (blk & 255) << 6;
        const float* f3 = feat3d + (size_t)b * 64 * NPTS + p0;
#pragma unroll
        for (int it = 0; it < 16; it++) {
            int i = it * 256 + tid;
            int c = i >> 6, pt = i & 63;
            sT[c * 67 + pt] = f3[(size_t)c * NPTS + pt];
        }
        if (tid < 128) {
            int c = tid >> 6, pt = tid & 63;
            sT[(64 + c) * 67 + pt] = flow3d[((size_t)b * 2 + c) * NPTS + p0 + pt];
            sT[(66 + c) * 67 + pt] = xy[((size_t)b * 2 + c) * NPTS + p0 + pt];
        }
        __syncthreads();
        float* dst = g_T + ((size_t)(b << 14) + p0) * 68;
#pragma unroll
        for (int it = 0; it < 17; it++) {
            int i = it * 256 + tid;
            int pt = i / 68;
            int c = i - pt * 68;
            dst[i] = sT[c * 67 + pt];
        }
    } else {
        int i = (blk - 1024) * 256 + tid;   // 0..23551 = n*368 + c
        int n = i / 368;
        int c = i - n * 368;
        int l, k;
        if (c < 88)       { l = 0; k = c; }
        else if (c < 160) { l = 1; k = c - 88; }
        else if (c < 232) { l = 2; k = c - 160; }
        else              { l = 3; k = c - 232; }
        const int KR[4]  = {69, 64, 64, 128};
        const int STR[4] = {176, 144, 144, 272};
        const int BH[4]  = {BH1, BH2, BH3, BH4};
        const int BL[4]  = {BL1, BL2, BL3, BL4};
        const float* src = (l == 0) ? w1 : (l == 1) ? w2 : (l == 2) ? w3 : wf;
        float v = (k < KR[l]) ? src[n * KR[l] + k] : 0.0f;
        int col = (l == 0) ? ((k < 3) ? k : k + 1) : k;
        float hf = __bfloat162float(__float2bfloat16_rn(v));
        unsigned short hb = __bfloat16_as_ushort(__float2bfloat16_rn(v));
        unsigned short lb = __bfloat16_as_ushort(__float2bfloat16_rn(v - hf));
        if (col * 2 < STR[l]) {
            int off = n * STR[l] + col * 2;
            *(unsigned short*)(g_W + BH[l] + off) = hb;
            *(unsigned short*)(g_W + BL[l] + off) = lb;
        }
        if (l == 0 && k == 87) {
            int off = n * 176 + 3 * 2;
            *(unsigned short*)(g_W + BH1 + off) = 0;
            *(unsigned short*)(g_W + BL1 + off) = 0;
        }
    }
}

// ---------------- per-warp GEMM layer: M=32 (group's pixels), N=16 ----------------
__device__ __forceinline__ void run_layer(float* acc, uint32_t aBase, int strideA,
                                          int loAoff, int ksegs,
                                          uint32_t bHi, uint32_t bLo, int strideB,
                                          int lane, int warpPix, int nBase) {
    const int g = lane >> 3, r = lane & 7;
    const int aRow  = ((g & 1) << 3) + r;
    const int aColB = (g >> 1) << 4;
    const int bRow  = ((g >> 1) << 3) + r;
    const int bColB = (g & 1) << 4;
    const uint32_t aAddr = aBase + (uint32_t)(warpPix + aRow) * strideA + aColB;
    const uint32_t bhAddr = bHi + (uint32_t)(nBase + bRow) * strideB + bColB;
    const uint32_t blAddr = bLo + (uint32_t)(nBase + bRow) * strideB + bColB;

#pragma unroll
    for (int j = 0; j < ksegs; j++) {
        const uint32_t ja = (uint32_t)(j << 5);
        uint32_t Ah0[4], Ah1[4], Al0[4], Al1[4], Bh[4], Bl[4];
        LDSM4(Ah0[0], Ah0[1], Ah0[2], Ah0[3], aAddr + ja);
        LDSM4(Ah1[0], Ah1[1], Ah1[2], Ah1[3], aAddr + ja + 16u * strideA);
        LDSM4(Al0[0], Al0[1], Al0[2], Al0[3], aAddr + ja + loAoff);
        LDSM4(Al1[0], Al1[1], Al1[2], Al1[3], aAddr + ja + loAoff + 16u * strideA);
        LDSM4(Bh[0], Bh[1], Bh[2], Bh[3], bhAddr + ja);
        LDSM4(Bl[0], Bl[1], Bl[2], Bl[3], blAddr + ja);
#pragma unroll
        for (int nt = 0; nt < 2; nt++) {
            uint32_t bh0 = Bh[nt << 1], bh1 = Bh[(nt << 1) + 1];
            uint32_t bl0 = Bl[nt << 1], bl1 = Bl[(nt << 1) + 1];
            float* c0 = acc + nt * 4;
            float* c1 = acc + 8 + nt * 4;
            MMA16816(c0, Ah0[0], Ah0[1], Ah0[2], Ah0[3], bh0, bh1);
            MMA16816(c1, Ah1[0], Ah1[1], Ah1[2], Ah1[3], bh0, bh1);
            MMA16816(c0, Al0[0], Al0[1], Al0[2], Al0[3], bh0, bh1);
            MMA16816(c1, Al1[0], Al1[1], Al1[2], Al1[3], bh0, bh1);
            MMA16816(c0, Ah0[0], Ah0[1], Ah0[2], Ah0[3], bl0, bl1);
            MMA16816(c1, Ah1[0], Ah1[1], Ah1[2], Ah1[3], bl0, bl1);
        }
    }
}

// epilogue: bias + lrelu + split-bf16 store into next A tile (16 N-columns)
__device__ __forceinline__ void epi_store(const float* acc, const float* bias,
                                          char* dst, int strideA, int loOffB,
                                          int lane, int warpPix, int nBase) {
    const int r = lane >> 2;
    const int nb = (lane & 3) << 1;
#pragma unroll
    for (int mt = 0; mt < 2; mt++) {
        char* p0 = dst + (warpPix + (mt << 4) + r) * strideA;
        char* p1 = p0 + 8 * strideA;
#pragma unroll
        for (int nt = 0; nt < 2; nt++) {
            const float* c = acc + mt * 8 + nt * 4;
            const int n = nBase + (nt << 3) + nb;
            float b0 = bias[n], b1 = bias[n + 1];
            float v00 = lrelu(c[0] + b0), v01 = lrelu(c[1] + b1);
            float v10 = lrelu(c[2] + b0), v11 = lrelu(c[3] + b1);
            *(uint32_t*)(p0 + n * 2)          = pack2(v00, v01);
            *(uint32_t*)(p0 + loOffB + n * 2) = pack2(lo_of(v00), lo_of(v01));
            *(uint32_t*)(p1 + n * 2)          = pack2(v10, v11);
            *(uint32_t*)(p1 + loOffB + n * 2) = pack2(lo_of(v10), lo_of(v11));
        }
    }
}

// ---------------- fused kernel ----------------
__global__ __launch_bounds__(NT, 1)
void fused_kernel(const float* __restrict__ feat2d,
                  const float* __restrict__ lf2d,
                  const int*   __restrict__ nnp,
                  const float* __restrict__ b1, const float* __restrict__ b2,
                  const float* __restrict__ b3, const float* __restrict__ bfin,
                  float* __restrict__ out) {
    extern __shared__ char smem[];
    const uint32_t s32 = smem_u32(smem);
    const int tid  = threadIdx.x;
    const int lane = tid & 31;
    const int wid  = tid >> 5;
    const int grp  = wid >> 2;             // pixel group 0..3
    const int warpPix = grp << 5;          // group's row base
    const int nBase   = (wid & 3) << 4;    // N-quarter (0,16,32,48)
    const int barid   = 1 + grp;
    // prologue decomposition: thread = (pixel p32 in group, channel quarter q)
    const int t    = tid & 127;
    const int p32  = t & 31;
    const int q    = t >> 5;
    const int prow = warpPix + p32;        // tile row = pixel index in tile

    // ---- one-time: weights + bias into SMEM ----
    {
        const uint4* src = (const uint4*)g_W;
        uint4* dst = (uint4*)(smem + SM_B);
        for (int i = tid; i < WBYTES / 16; i += NT) dst[i] = src[i];
        float* sb = (float*)(smem + SM_BIAS);
        if (tid < 64) {
            sb[tid]       = b1[tid];
            sb[64 + tid]  = b2[tid];
            sb[128 + tid] = b3[tid];
            sb[192 + tid] = bfin[tid];
        }
    }
    __syncthreads();
    const float* sbias = (const float*)(smem + SM_BIAS);
    float* scr = (float*)(smem + SM_SCR);

    for (int tile = blockIdx.x; tile < NTILES; tile += gridDim.x) {
        const int gp  = (tile << 7) + prow;
        const int b   = gp >> 16;
        const int pix = gp & 65535;

        // ---------- prologue: channels [16q, 16q+16) of pixel prow ----------
        {
            const int idx = nnp[gp];
            const float* t3 = g_T + (size_t)((b << 14) + idx) * 68;
            float av[16];
            const float* t3h = t3 + (q << 4);
#pragma unroll
            for (int k = 0; k < 16; k += 4) {
                float4 v = *(const float4*)(t3h + k);
                av[k] = v.x; av[k + 1] = v.y; av[k + 2] = v.z; av[k + 3] = v.w;
            }
            float4 tv = make_float4(0.f, 0.f, 0.f, 0.f);
            float lfx = 0.f, lfy = 0.f;
            if (q == 3) {
                tv = *(const float4*)(t3 + 64);        // fl0, fl1, xyx, xyy
                const float* lf = lf2d + (((size_t)b * 2) << 16) + pix;
                lfx = lf[0]; lfy = lf[65536];
            }

            char* A4p = smem + SM_A4 + prow * STRIDE_A4;
            const float* f2p = feat2d + (((size_t)(b * 64 + (q << 4))) << 16) + pix;
            float pc = 0.0f;
#pragma unroll
            for (int c = 0; c < 16; c += 2) {
                float v0 = f2p[(size_t)c << 16];
                float v1 = f2p[(size_t)(c + 1) << 16];
                pc += av[c] * v0 + av[c + 1] * v1;
                *(uint32_t*)(A4p + 128 + (q << 5) + c * 2) = pack2(v0, v1);
                *(uint32_t*)(A4p + 384 + (q << 5) + c * 2) = pack2(lo_of(v0), lo_of(v1));
            }
            char* A1p = smem + SM_A1 + prow * STRIDE_A1;
#pragma unroll
            for (int k = 0; k < 16; k += 2) {
                int cb = (4 + (q << 4) + k) * 2;
                *(uint32_t*)(A1p + cb)       = pack2(av[k], av[k + 1]);
                *(uint32_t*)(A1p + 160 + cb) = pack2(lo_of(av[k]), lo_of(av[k + 1]));
            }
            scr[tid] = pc;
            GBAR(barid);
            if (q == 3) {
                const int sb0 = (grp << 7) + p32;
                float corr = (scr[sb0] + scr[sb0 + 32] + scr[sb0 + 64] + pc)
                             * (1.0f / 64.0f);
                float offx = tv.z - (float)(pix & 255);
                float offy = tv.w - (float)(pix >> 8);
                float fl0 = tv.x - lfx, fl1 = tv.y - lfy;
                *(uint32_t*)(A1p + 0)   = pack2(corr, offx);
                *(uint32_t*)(A1p + 4)   = pack2(offy, 0.0f);
                *(uint32_t*)(A1p + 160) = pack2(lo_of(corr), lo_of(offx));
                *(uint32_t*)(A1p + 164) = pack2(lo_of(offy), 0.0f);
                *(uint32_t*)(A1p + 136) = pack2(fl0, fl1);          // cols 68,69
                *(uint32_t*)(A1p + 296) = pack2(lo_of(fl0), lo_of(fl1));
#pragma unroll
                for (int z = 0; z < 5; z++) {                        // cols 70..79 zero
                    *(uint32_t*)(A1p + 140 + z * 4) = 0u;
                    *(uint32_t*)(A1p + 300 + z * 4) = 0u;
                }
            }
        }
        GBAR(barid);

        float acc[16];

        // ---- layer 1: K=80 ----
#pragma unroll
        for (int i = 0; i < 16; i++) acc[i] = 0.0f;
        run_layer(acc, s32 + SM_A1, STRIDE_A1, 160, 5,
                  s32 + SM_B + BH1, s32 + SM_B + BL1, 176, lane, warpPix, nBase);
        GBAR(barid);   // RACE FIX: all group warps finish READING A1 before overwrite
        epi_store(acc, sbias, smem + SM_A1, STRIDE_A1, 128, lane, warpPix, nBase);
        GBAR(barid);

        // ---- layer 2 ----
#pragma unroll
        for (int i = 0; i < 16; i++) acc[i] = 0.0f;
        run_layer(acc, s32 + SM_A1, STRIDE_A1, 128, 4,
                  s32 + SM_B + BH2, s32 + SM_B + BL2, 144, lane, warpPix, nBase);
        GBAR(barid);   // RACE FIX: reads-before-overwrite
        epi_store(acc, sbias + 64, smem + SM_A1, STRIDE_A1, 128, lane, warpPix, nBase);
        GBAR(barid);

        // ---- layer 3 -> x3 into L4 A tile (disjoint from A1: no pre-epi barrier) ----
#pragma unroll
        for (int i = 0; i < 16; i++) acc[i] = 0.0f;
        run_layer(acc, s32 + SM_A1, STRIDE_A1, 128, 4,
                  s32 + SM_B + BH3, s32 + SM_B + BL3, 144, lane, warpPix, nBase);
        epi_store(acc, sbias + 128, smem + SM_A4, STRIDE_A4, 256, lane, warpPix, nBase);
        GBAR(barid);

        // ---- layer 4: K=128 ----
#pragma unroll
        for (int i = 0; i < 16; i++) acc[i] = 0.0f;
        run_layer(acc, s32 + SM_A4, STRIDE_A4, 256, 8,
                  s32 + SM_B + BH4, s32 + SM_B + BL4, 272, lane, warpPix, nBase);

        // ---- output: direct STG from fragments ----
        {
            const int pixbase = (tile << 7) & 65535;
            const int r = lane >> 2;
            const int nb = (lane & 3) << 1;
            float* ob = out + ((size_t)b << 22) + pixbase;
#pragma unroll
            for (int mt = 0; mt < 2; mt++) {
                float* p0 = ob + warpPix + (mt << 4) + r;
                float* p1 = p0 + 8;
#pragma unroll
                for (int nt = 0; nt < 2; nt++) {
                    const float* c = acc + mt * 8 + nt * 4;
                    const int n = nBase + (nt << 3) + nb;
                    float bb0 = sbias[192 + n], bb1 = sbias[192 + n + 1];
                    p0[(size_t)n << 16]       = lrelu(c[0] + bb0);
                    p0[(size_t)(n + 1) << 16] = lrelu(c[1] + bb1);
                    p1[(size_t)n << 16]       = lrelu(c[2] + bb0);
                    p1[(size_t)(n + 1) << 16] = lrelu(c[3] + bb1);
                }
            }
        }
        GBAR(barid);   // A4 (and A1) fully consumed before next prologue writes
    }
}

extern "C" void kernel_launch(void* const* d_in, const int* in_sizes, int n_in,
                              void* d_out, int out_size) {
    const float* xy    = (const float*)d_in[0];
    const float* f2d   = (const float*)d_in[1];
    const float* f3d   = (const float*)d_in[2];
    const float* lf2d  = (const float*)d_in[3];
    const float* lf3d  = (const float*)d_in[4];
    const int*   nnp   = (const int*)d_in[5];
    const float* w1 = (const float*)d_in[6];
    const float* b1 = (const float*)d_in[7];
    const float* w2 = (const float*)d_in[8];
    const float* b2 = (const float*)d_in[9];
    const float* w3 = (const float*)d_in[10];
    const float* b3 = (const float*)d_in[11];
    const float* wf = (const float*)d_in[12];
    const float* bf = (const float*)d_in[13];
    float* out = (float*)d_out;

    cudaFuncSetAttribute(fused_kernel,
                         cudaFuncAttributeMaxDynamicSharedMemorySize, SMEM_TOTAL);

    prep_kernel<<<1024 + 92, 256>>>(xy, f3d, lf3d, w1, w2, w3, wf);
    fused_kernel<<<148, NT, SMEM_TOTAL>>>(f2d, lf2d, nnp, b1, b2, b3, bf, out);
}